// round 4
// baseline (speedup 1.0000x reference)
#include <cuda_runtime.h>
#include <cuda_bf16.h>
#include <mma.h>
#include <cstdint>

using namespace nvcuda;

// ---------------------------------------------------------------------------
// GAT 4-layer network, N=50000 nodes, E=800000 edges (+ N self-loops).
// dims: 256 -> 32 -> 64 -> 128 -> 128 -> fc 40
// R4: bf16x3 (Dekker-split) tensor-core GEMM with producer-side splitting,
//     one-exp-per-edge 3-phase edge kernel with vector gathers.
// ---------------------------------------------------------------------------

#define NMAX 50000
#define NPAD 50048
#define EMAX 800000
#define CMAX 128
#define TOTE (EMAX + NMAX)

// -------------------- device scratch (allocation-free rule) ---------------
__device__ int      g_src[EMAX];
__device__ int      g_dst[EMAX];
__device__ int      g_cnt[NMAX];
__device__ int      g_rowptr[NMAX + 1];
__device__ int      g_cursor[NMAX];
__device__ int      g_csr_src[TOTE];
__device__ int      g_blocksum[512];
__device__ float    g_e[TOTE];
__device__ __align__(16) float g_h[(size_t)NPAD * CMAX];        // gemm out (fp32)
__device__ __align__(16) __nv_bfloat16 g_xhi[(size_t)NPAD * 256];
__device__ __align__(16) __nv_bfloat16 g_xlo[(size_t)NPAD * 256];
__device__ __align__(16) __nv_bfloat16 g_aAhi[(size_t)NPAD * CMAX];
__device__ __align__(16) __nv_bfloat16 g_aAlo[(size_t)NPAD * CMAX];
__device__ __align__(16) __nv_bfloat16 g_aBhi[(size_t)NPAD * CMAX];
__device__ __align__(16) __nv_bfloat16 g_aBlo[(size_t)NPAD * CMAX];
__device__ __align__(16) __nv_bfloat16 g_Whi[64 * 1024];        // all 4 W's packed
__device__ __align__(16) __nv_bfloat16 g_Wlo[64 * 1024];
__device__ float    g_es[NMAX];
__device__ float    g_ed[NMAX];
__device__ int      g_is64;

// W pack offsets (elements)
#define W1_OFF 0
#define W2_OFF (256 * 32)
#define W3_OFF (W2_OFF + 32 * 64)
#define W4_OFF (W3_OFF + 64 * 128)
#define W_TOTAL (W4_OFF + 128 * 128)

__device__ __forceinline__ void dsplit(float v, __nv_bfloat16& h, __nv_bfloat16& l) {
    h = __float2bfloat16(v);
    l = __float2bfloat16(v - __bfloat162float(h));
}

// -------------------- edge dtype detection + normalization ----------------
__global__ void detect_kernel(const void* eptr) {
    if (threadIdx.x == 0 && blockIdx.x == 0) {
        const int* p = (const int*)eptr;
        int all0 = 1;
        for (int i = 1; i < 128; i += 2)
            if (p[i] != 0) all0 = 0;
        g_is64 = all0;
    }
}

__global__ void convert_kernel(const void* eptr, int E, int n) {
    int i = blockIdx.x * blockDim.x + threadIdx.x;
    if (i < n) g_cnt[i] = 0;
    if (i >= E) return;
    if (g_is64) {
        const long long* p = (const long long*)eptr;
        g_src[i] = (int)p[i];
        g_dst[i] = (int)p[E + i];
    } else {
        const int* p = (const int*)eptr;
        g_src[i] = p[i];
        g_dst[i] = p[E + i];
    }
}

// -------------------- x split: fp32 -> bf16 hi/lo --------------------------
__global__ void splitx_kernel(const float* __restrict__ src, int total4) {
    int i = blockIdx.x * blockDim.x + threadIdx.x;
    if (i >= total4) return;
    float4 v = reinterpret_cast<const float4*>(src)[i];
    __nv_bfloat16 h0, l0, h1, l1, h2, l2, h3, l3;
    dsplit(v.x, h0, l0); dsplit(v.y, h1, l1);
    dsplit(v.z, h2, l2); dsplit(v.w, h3, l3);
    reinterpret_cast<__nv_bfloat162*>(g_xhi)[2 * i]     = {h0, h1};
    reinterpret_cast<__nv_bfloat162*>(g_xhi)[2 * i + 1] = {h2, h3};
    reinterpret_cast<__nv_bfloat162*>(g_xlo)[2 * i]     = {l0, l1};
    reinterpret_cast<__nv_bfloat162*>(g_xlo)[2 * i + 1] = {l2, l3};
}

// -------------------- weight split: all 4 W's packed ----------------------
__global__ void splitw_kernel(const float* __restrict__ W1, const float* __restrict__ W2,
                              const float* __restrict__ W3, const float* __restrict__ W4) {
    int i = blockIdx.x * blockDim.x + threadIdx.x;
    if (i >= W_TOTAL) return;
    float v;
    if      (i < W2_OFF) v = W1[i - W1_OFF];
    else if (i < W3_OFF) v = W2[i - W2_OFF];
    else if (i < W4_OFF) v = W3[i - W3_OFF];
    else                 v = W4[i - W4_OFF];
    __nv_bfloat16 h, l;
    dsplit(v, h, l);
    g_Whi[i] = h;
    g_Wlo[i] = l;
}

// -------------------- CSR build: count / scan / scatter -------------------
__global__ void count_kernel(int E, int n) {
    int idx = blockIdx.x * blockDim.x + threadIdx.x;
    if (idx >= E + n) return;
    int d = (idx < E) ? g_dst[idx] : idx - E;
    atomicAdd(&g_cnt[d], 1);
}

__global__ void scan1_kernel(int n) {
    int tid = threadIdx.x;
    int idx = blockIdx.x * 256 + tid;
    int v = (idx < n) ? g_cnt[idx] : 0;
    int lane = tid & 31, w = tid >> 5;
#pragma unroll
    for (int o = 16; o; o >>= 1) v += __shfl_down_sync(0xffffffffu, v, o);
    __shared__ int ws[8];
    if (lane == 0) ws[w] = v;
    __syncthreads();
    if (tid == 0) {
        int s = 0;
#pragma unroll
        for (int i = 0; i < 8; i++) s += ws[i];
        g_blocksum[blockIdx.x] = s;
    }
}

__global__ void scan2_kernel(int nb) {
    int lane = threadIdx.x;
    int off = 0;
    for (int base = 0; base < nb; base += 32) {
        int idx = base + lane;
        int v = (idx < nb) ? g_blocksum[idx] : 0;
        int x = v;
#pragma unroll
        for (int o = 1; o < 32; o <<= 1) {
            int y = __shfl_up_sync(0xffffffffu, x, o);
            if (lane >= o) x += y;
        }
        if (idx < nb) g_blocksum[idx] = x - v + off;
        off += __shfl_sync(0xffffffffu, x, 31);
    }
}

__global__ void scan3_kernel(int n) {
    int tid = threadIdx.x;
    int idx = blockIdx.x * 256 + tid;
    int v = (idx < n) ? g_cnt[idx] : 0;
    int lane = tid & 31, w = tid >> 5;
    unsigned full = 0xffffffffu;
    int x = v;
#pragma unroll
    for (int o = 1; o < 32; o <<= 1) {
        int y = __shfl_up_sync(full, x, o);
        if (lane >= o) x += y;
    }
    __shared__ int wsum[8];
    __shared__ int woff[8];
    if (lane == 31) wsum[w] = x;
    __syncthreads();
    if (tid < 8) {
        int s = wsum[tid];
#pragma unroll
        for (int o = 1; o < 8; o <<= 1) {
            int y = __shfl_up_sync(0xffu, s, o);
            if (tid >= o) s += y;
        }
        woff[tid] = s - wsum[tid];
    }
    __syncthreads();
    int excl = x - v + woff[w] + g_blocksum[blockIdx.x];
    if (idx < n) {
        g_rowptr[idx] = excl;
        g_cursor[idx] = excl;
        if (idx == n - 1) g_rowptr[n] = excl + v;
    }
}

__global__ void scatter_kernel(int E, int n) {
    int idx = blockIdx.x * blockDim.x + threadIdx.x;
    if (idx >= E + n) return;
    int s, d;
    if (idx < E) { s = g_src[idx]; d = g_dst[idx]; }
    else         { s = d = idx - E; }
    int pos = atomicAdd(&g_cursor[d], 1);
    g_csr_src[pos] = s;
}

// -------------------- GEMM: h = A @ W  (bf16x3, pre-split operands) -------
// A, W given as bf16 hi/lo pairs. D += a_lo*b_hi + a_hi*b_lo + a_hi*b_hi.
template <int CIN, int COUT>
__global__ void gemm_bf16_kernel(const __nv_bfloat16* __restrict__ Ahi,
                                 const __nv_bfloat16* __restrict__ Alo,
                                 const __nv_bfloat16* __restrict__ Bhi,
                                 const __nv_bfloat16* __restrict__ Blo,
                                 float* __restrict__ outp) {
    constexpr int KC = 32;
    constexpr int WN = (COUT >= 64) ? 4 : COUT / 16;   // warps along N
    constexpr int NTILE = COUT / 16 / WN;              // 16-col tiles per warp
    constexpr int WM = 2;                              // warps along M (32 rows)
    constexpr int T = 32 * WM * WN;

    __shared__ __nv_bfloat16 sAh[32 * KC], sAl[32 * KC];
    __shared__ __nv_bfloat16 sBh[KC * COUT], sBl[KC * COUT];

    int tid = threadIdx.x;
    int wid = tid >> 5;
    int warp_m = wid / WN, warp_n = wid % WN;
    size_t row0 = (size_t)blockIdx.x * 32;

    wmma::fragment<wmma::accumulator, 16, 16, 16, float> acc[NTILE];
#pragma unroll
    for (int t = 0; t < NTILE; t++) wmma::fill_fragment(acc[t], 0.0f);

    for (int kc = 0; kc < CIN; kc += KC) {
        // A chunk: 32 x KC (uint2 = 4 bf16 per load)
#pragma unroll
        for (int i = tid; i < 32 * KC / 4; i += T) {
            int r = i / (KC / 4);
            int c = (i % (KC / 4)) * 4;
            *(uint2*)(sAh + r * KC + c) =
                *(const uint2*)(Ahi + (row0 + r) * CIN + kc + c);
            *(uint2*)(sAl + r * KC + c) =
                *(const uint2*)(Alo + (row0 + r) * CIN + kc + c);
        }
        // B chunk: KC x COUT (row-major, contiguous)
#pragma unroll
        for (int i = tid; i < KC * COUT / 4; i += T) {
            int c = i * 4;
            *(uint2*)(sBh + c) = *(const uint2*)(Bhi + (size_t)kc * COUT + c);
            *(uint2*)(sBl + c) = *(const uint2*)(Blo + (size_t)kc * COUT + c);
        }
        __syncthreads();

#pragma unroll
        for (int k16 = 0; k16 < KC; k16 += 16) {
            wmma::fragment<wmma::matrix_a, 16, 16, 16, __nv_bfloat16, wmma::row_major> ah, al;
            wmma::load_matrix_sync(ah, sAh + (warp_m * 16) * KC + k16, KC);
            wmma::load_matrix_sync(al, sAl + (warp_m * 16) * KC + k16, KC);
#pragma unroll
            for (int t = 0; t < NTILE; t++) {
                int nc = (warp_n + t * WN) * 16;
                wmma::fragment<wmma::matrix_b, 16, 16, 16, __nv_bfloat16, wmma::row_major> bh, bl;
                wmma::load_matrix_sync(bh, sBh + k16 * COUT + nc, COUT);
                wmma::load_matrix_sync(bl, sBl + k16 * COUT + nc, COUT);
                wmma::mma_sync(acc[t], al, bh, acc[t]);
                wmma::mma_sync(acc[t], ah, bl, acc[t]);
                wmma::mma_sync(acc[t], ah, bh, acc[t]);
            }
        }
        __syncthreads();
    }

#pragma unroll
    for (int t = 0; t < NTILE; t++) {
        int nc = (warp_n + t * WN) * 16;
        wmma::store_matrix_sync(outp + (row0 + warp_m * 16) * COUT + nc,
                                acc[t], COUT, wmma::mem_row_major);
    }
}

// -------------------- per-row attention dots: es = h.a_s, ed = h.a_d ------
__global__ void edot_kernel(const float* __restrict__ as_,
                            const float* __restrict__ ad_, int n, int cout) {
    int warp = (blockIdx.x * blockDim.x + threadIdx.x) / 32;
    int lane = threadIdx.x & 31;
    if (warp >= n) return;
    const float* hrow = g_h + (size_t)warp * cout;
    float s = 0.f, d = 0.f;
    for (int c = lane; c < cout; c += 32) {
        float v = hrow[c];
        s = fmaf(v, as_[c], s);
        d = fmaf(v, ad_[c], d);
    }
#pragma unroll
    for (int off = 16; off > 0; off >>= 1) {
        s += __shfl_down_sync(0xffffffffu, s, off);
        d += __shfl_down_sync(0xffffffffu, d, off);
    }
    if (lane == 0) { g_es[warp] = s; g_ed[warp] = d; }
}

// -------------------- vector helpers --------------------------------------
template <int V> struct VecT;
template <> struct VecT<1> { using T = float; };
template <> struct VecT<2> { using T = float2; };
template <> struct VecT<4> { using T = float4; };

__device__ __forceinline__ void vfma(float& a, float al, float v) {
    a = fmaf(al, v, a);
}
__device__ __forceinline__ void vfma(float2& a, float al, float2 v) {
    a.x = fmaf(al, v.x, a.x); a.y = fmaf(al, v.y, a.y);
}
__device__ __forceinline__ void vfma(float4& a, float al, float4 v) {
    a.x = fmaf(al, v.x, a.x); a.y = fmaf(al, v.y, a.y);
    a.z = fmaf(al, v.z, a.z); a.w = fmaf(al, v.w, a.w);
}

// relu + Dekker-split store of a V-vector into bf16 hi/lo arrays
__device__ __forceinline__ void store_split(float v, __nv_bfloat16* hi,
                                            __nv_bfloat16* lo) {
    float r = fmaxf(v, 0.0f);
    __nv_bfloat16 h, l;
    dsplit(r, h, l);
    *hi = h; *lo = l;
}
__device__ __forceinline__ void store_split_vec(float acc, __nv_bfloat16* hi,
                                                __nv_bfloat16* lo) {
    store_split(acc, hi, lo);
}
__device__ __forceinline__ void store_split_vec(float2 acc, __nv_bfloat16* hi,
                                                __nv_bfloat16* lo) {
    float r0 = fmaxf(acc.x, 0.f), r1 = fmaxf(acc.y, 0.f);
    __nv_bfloat16 h0, l0, h1, l1;
    dsplit(r0, h0, l0); dsplit(r1, h1, l1);
    *reinterpret_cast<__nv_bfloat162*>(hi) = {h0, h1};
    *reinterpret_cast<__nv_bfloat162*>(lo) = {l0, l1};
}
__device__ __forceinline__ void store_split_vec(float4 acc, __nv_bfloat16* hi,
                                                __nv_bfloat16* lo) {
    float r0 = fmaxf(acc.x, 0.f), r1 = fmaxf(acc.y, 0.f);
    float r2 = fmaxf(acc.z, 0.f), r3 = fmaxf(acc.w, 0.f);
    __nv_bfloat16 h0, l0, h1, l1, h2, l2, h3, l3;
    dsplit(r0, h0, l0); dsplit(r1, h1, l1);
    dsplit(r2, h2, l2); dsplit(r3, h3, l3);
    reinterpret_cast<__nv_bfloat162*>(hi)[0] = {h0, h1};
    reinterpret_cast<__nv_bfloat162*>(hi)[1] = {h2, h3};
    reinterpret_cast<__nv_bfloat162*>(lo)[0] = {l0, l1};
    reinterpret_cast<__nv_bfloat162*>(lo)[1] = {l2, l3};
}

// -------------------- fused edge phase: softmax + aggregate (warp/dst) ----
// Writes relu(bias + sum alpha*h[src]) as Dekker-split bf16 hi/lo (next-layer
// GEMM input format). One exp per edge.
template <int COUT>
__global__ void gat_edge_kernel(const float* __restrict__ b,
                                __nv_bfloat16* __restrict__ ahi,
                                __nv_bfloat16* __restrict__ alo, int n) {
    constexpr int V = COUT / 32;
    using VT = typename VecT<V>::T;
    int lane = threadIdx.x & 31;
    int d = blockIdx.x * 8 + (threadIdx.x >> 5);
    if (d >= n) return;

    int r0 = g_rowptr[d];
    int r1 = g_rowptr[d + 1];
    float edd = g_ed[d];

    // phase 1: e = leaky_relu(es[src]+ed[dst]); warp max
    float mx = -3.4e38f;
    for (int i = r0 + lane; i < r1; i += 32) {
        float e = __ldg(&g_es[__ldg(&g_csr_src[i])]) + edd;
        e = (e > 0.f) ? e : 0.2f * e;
        g_e[i] = e;
        mx = fmaxf(mx, e);
    }
#pragma unroll
    for (int o = 16; o; o >>= 1) mx = fmaxf(mx, __shfl_xor_sync(0xffffffffu, mx, o));

    // phase 2: exp once per edge, store; warp sum
    float sum = 0.f;
    for (int i = r0 + lane; i < r1; i += 32) {
        float ex = __expf(g_e[i] - mx);
        g_e[i] = ex;
        sum += ex;
    }
#pragma unroll
    for (int o = 16; o; o >>= 1) sum += __shfl_xor_sync(0xffffffffu, sum, o);
    float invS = 1.0f / sum;
    __syncwarp();

    // phase 3: acc = bias + sum alpha * h[src]   (lane owns V columns)
    const VT* bv = reinterpret_cast<const VT*>(b);
    VT acc = __ldg(&bv[lane]);
    const VT* hv = reinterpret_cast<const VT*>(g_h);

#pragma unroll 4
    for (int i = r0; i < r1; i++) {
        int sidx = __ldg(&g_csr_src[i]);
        float alpha = __ldg(&g_e[i]) * invS;
        VT v = __ldg(&hv[(size_t)sidx * 32 + lane]);
        vfma(acc, alpha, v);
    }
    store_split_vec(acc, ahi + (size_t)d * COUT + lane * V,
                         alo + (size_t)d * COUT + lane * V);
}

// -------------------- final FC: out = relu(agg4) @ fcW + fcb --------------
__global__ void fc_kernel(const __nv_bfloat16* __restrict__ inhi,
                          const __nv_bfloat16* __restrict__ inlo,
                          const float* __restrict__ fcW,
                          const float* __restrict__ fcb,
                          float* __restrict__ out, int n) {
    __shared__ float Ws[128 * 40];
    int tid = threadIdx.x;                 // blockDim = 320
    for (int i = tid; i < 128 * 40; i += 320) Ws[i] = fcW[i];
    __syncthreads();
    int tx = tid % 40;
    int ty = tid / 40;                     // 8 rows/block
    int row = blockIdx.x * 8 + ty;
    if (row >= n) return;
    const __nv_bfloat16* ih = inhi + (size_t)row * 128;
    const __nv_bfloat16* il = inlo + (size_t)row * 128;
    float acc = 0.f;
#pragma unroll 8
    for (int k = 0; k < 128; k++) {
        float v = __bfloat162float(ih[k]) + __bfloat162float(il[k]);
        acc = fmaf(v, Ws[k * 40 + tx], acc);
    }
    out[(size_t)row * 40 + tx] = acc + fcb[tx];
}

// ---------------------------------------------------------------------------
// host driver
// ---------------------------------------------------------------------------
static inline int ceil_div(int a, int b) { return (a + b - 1) / b; }

extern "C" void kernel_launch(void* const* d_in, const int* in_sizes, int n_in,
                              void* d_out, int out_size) {
    const float* x   = (const float*)d_in[0];
    const void*  ei  = d_in[1];
    const float* W1  = (const float*)d_in[2];
    const float* a1s = (const float*)d_in[3];
    const float* a1d = (const float*)d_in[4];
    const float* b1  = (const float*)d_in[5];
    const float* W2  = (const float*)d_in[6];
    const float* a2s = (const float*)d_in[7];
    const float* a2d = (const float*)d_in[8];
    const float* b2  = (const float*)d_in[9];
    const float* W3  = (const float*)d_in[10];
    const float* a3s = (const float*)d_in[11];
    const float* a3d = (const float*)d_in[12];
    const float* b3  = (const float*)d_in[13];
    const float* W4  = (const float*)d_in[14];
    const float* a4s = (const float*)d_in[15];
    const float* a4d = (const float*)d_in[16];
    const float* b4  = (const float*)d_in[17];
    const float* fcW = (const float*)d_in[18];
    const float* fcb = (const float*)d_in[19];

    const int n = in_sizes[0] / 256;
    const int E = in_sizes[1] / 2;
    const int tot = E + n;
    const int nb = ceil_div(n, 256);
    const int nblk32 = ceil_div(n, 32);    // gemm blocks (32 rows each)

    __nv_bfloat16 *xhi, *xlo, *Whi, *Wlo;
    __nv_bfloat16 *aAhi, *aAlo, *aBhi, *aBlo;
    float* h;
    cudaGetSymbolAddress((void**)&xhi, g_xhi);
    cudaGetSymbolAddress((void**)&xlo, g_xlo);
    cudaGetSymbolAddress((void**)&Whi, g_Whi);
    cudaGetSymbolAddress((void**)&Wlo, g_Wlo);
    cudaGetSymbolAddress((void**)&aAhi, g_aAhi);
    cudaGetSymbolAddress((void**)&aAlo, g_aAlo);
    cudaGetSymbolAddress((void**)&aBhi, g_aBhi);
    cudaGetSymbolAddress((void**)&aBlo, g_aBlo);
    cudaGetSymbolAddress((void**)&h, g_h);

    // ---- preprocessing (gemm1 placed 4th in stream order for profiling) ----
    detect_kernel<<<1, 32>>>(ei);                                   // 1
    splitx_kernel<<<ceil_div(n * 64, 256), 256>>>(x, n * 64);       // 2
    splitw_kernel<<<ceil_div(W_TOTAL, 256), 256>>>(W1, W2, W3, W4); // 3
    gemm_bf16_kernel<256, 32><<<nblk32, 128>>>(                    // 4 (profiled)
        xhi, xlo, Whi + W1_OFF, Wlo + W1_OFF, h);
    convert_kernel<<<ceil_div(E, 256), 256>>>(ei, E, n);            // 5
    count_kernel<<<ceil_div(tot, 256), 256>>>(E, n);                // 6
    scan1_kernel<<<nb, 256>>>(n);                                   // 7
    scan2_kernel<<<1, 32>>>(nb);                                    // 8
    scan3_kernel<<<nb, 256>>>(n);                                   // 9
    scatter_kernel<<<ceil_div(tot, 256), 256>>>(E, n);              // 10

    // ---- layer 1: 256 -> 32 (gemm already issued) ----
    edot_kernel<<<ceil_div(n, 8), 256>>>(a1s, a1d, n, 32);
    gat_edge_kernel<32><<<ceil_div(n, 8), 256>>>(b1, aAhi, aAlo, n);

    // ---- layer 2: 32 -> 64 ----
    gemm_bf16_kernel<32, 64><<<nblk32, 256>>>(aAhi, aAlo,
                                              Whi + W2_OFF, Wlo + W2_OFF, h);
    edot_kernel<<<ceil_div(n, 8), 256>>>(a2s, a2d, n, 64);
    gat_edge_kernel<64><<<ceil_div(n, 8), 256>>>(b2, aBhi, aBlo, n);

    // ---- layer 3: 64 -> 128 ----
    gemm_bf16_kernel<64, 128><<<nblk32, 256>>>(aBhi, aBlo,
                                               Whi + W3_OFF, Wlo + W3_OFF, h);
    edot_kernel<<<ceil_div(n, 8), 256>>>(a3s, a3d, n, 128);
    gat_edge_kernel<128><<<ceil_div(n, 8), 256>>>(b3, aAhi, aAlo, n);

    // ---- layer 4: 128 -> 128 ----
    gemm_bf16_kernel<128, 128><<<nblk32, 256>>>(aAhi, aAlo,
                                                Whi + W4_OFF, Wlo + W4_OFF, h);
    edot_kernel<<<ceil_div(n, 8), 256>>>(a4s, a4d, n, 128);
    gat_edge_kernel<128><<<ceil_div(n, 8), 256>>>(b4, aBhi, aBlo, n);

    // ---- final fc: relu(agg4) @ fcW + fcb ----
    fc_kernel<<<ceil_div(n, 8), 320>>>(aBhi, aBlo, fcW, fcb, (float*)d_out, n);
}

// round 5
// speedup vs baseline: 1.1419x; 1.1419x over previous
#include <cuda_runtime.h>
#include <cstdint>

// ---------------------------------------------------------------------------
// GAT 4-layer network, N=50000 nodes, E=800000 edges (+ N self-loops).
// dims: 256 -> 32 -> 64 -> 128 -> 128 -> fc 40
// R5: fp32 SIMT 4x4 GEMM with fused edot epilogue; register-resident
//     single-pass softmax edge kernel (deg<=32 fast path); slim preprocess.
// ---------------------------------------------------------------------------

#define NMAX 50000
#define EMAX 800000
#define CMAX 128
#define TOTE (EMAX + NMAX)

// -------------------- device scratch (allocation-free rule) ---------------
__device__ int      g_src[EMAX];
__device__ int      g_dst[EMAX];
__device__ int      g_cnt[NMAX];
__device__ int      g_rowptr[NMAX + 1];
__device__ int      g_cursor[NMAX];
__device__ int      g_csr_src[TOTE];
__device__ float    g_e[TOTE];
__device__ __align__(16) float g_h[(size_t)NMAX * CMAX];
__device__ __align__(16) float g_aggA[(size_t)NMAX * CMAX];
__device__ __align__(16) float g_aggB[(size_t)NMAX * CMAX];
__device__ float    g_es[NMAX];
__device__ float    g_ed[NMAX];
__device__ int      g_is64;

// -------------------- detect edge dtype + init counts ---------------------
__global__ void detect_init_kernel(const void* eptr, int n) {
    int i = blockIdx.x * blockDim.x + threadIdx.x;
    if (i < n) g_cnt[i] = 1;              // self-loop pre-counted
    if (i == 0) {
        const int* p = (const int*)eptr;
        int all0 = 1;
        for (int k = 1; k < 128; k += 2)
            if (p[k] != 0) all0 = 0;
        g_is64 = all0;   // int64 little-endian, values < 2^31 -> odd words 0
    }
}

// -------------------- convert + count (fused) ------------------------------
__global__ void convert_count_kernel(const void* eptr, int E) {
    int i = blockIdx.x * blockDim.x + threadIdx.x;
    if (i >= E) return;
    int s, d;
    if (g_is64) {
        const long long* p = (const long long*)eptr;
        s = (int)p[i];
        d = (int)p[E + i];
    } else {
        const int* p = (const int*)eptr;
        s = p[i];
        d = p[E + i];
    }
    g_src[i] = s;
    g_dst[i] = d;
    atomicAdd(&g_cnt[d], 1);
}

// -------------------- single-block exclusive scan over g_cnt --------------
__global__ void scan_kernel(int n) {
    const int T = 1024;
    int tid = threadIdx.x;
    int C = (n + T - 1) / T;
    int base = tid * C;
    int end = min(base + C, n);

    int s = 0;
    for (int k = base; k < end; k++) s += g_cnt[k];

    // block exclusive scan of s
    int lane = tid & 31, w = tid >> 5;
    unsigned full = 0xffffffffu;
    int x = s;
#pragma unroll
    for (int o = 1; o < 32; o <<= 1) {
        int y = __shfl_up_sync(full, x, o);
        if (lane >= o) x += y;
    }
    __shared__ int wsum[32];
    __shared__ int woff[32];
    if (lane == 31) wsum[w] = x;
    __syncthreads();
    if (tid < 32) {
        int v = wsum[tid];
        int xx = v;
#pragma unroll
        for (int o = 1; o < 32; o <<= 1) {
            int y = __shfl_up_sync(full, xx, o);
            if (tid >= o) xx += y;
        }
        woff[tid] = xx - v;
    }
    __syncthreads();
    int running = x - s + woff[w];

    for (int k = base; k < end; k++) {
        g_rowptr[k] = running;
        g_cursor[k] = running;
        running += g_cnt[k];
    }
    if (end == n && base < n) g_rowptr[n] = running;
}

__global__ void scatter_kernel(int E, int n) {
    int idx = blockIdx.x * blockDim.x + threadIdx.x;
    if (idx >= E + n) return;
    int s, d;
    if (idx < E) { s = g_src[idx]; d = g_dst[idx]; }
    else         { s = d = idx - E; }
    int pos = atomicAdd(&g_cursor[d], 1);
    g_csr_src[pos] = s;
}

// -------------------- GEMM + fused edot: h = act(in)@W; es,ed dots --------
template <int CIN, int COUT, bool RELU>
__global__ void gemm_kernel(const float* __restrict__ in,
                            const float* __restrict__ W,
                            const float* __restrict__ as_,
                            const float* __restrict__ ad_, int n) {
    constexpr int TX = COUT / 4;       // threads along column dim (float4 each)
    constexpr int TY = 256 / TX;       // thread-rows per block
    constexpr int R  = 4;              // rows per thread
    extern __shared__ float4 Ws[];     // CIN * TX float4

    int tid = threadIdx.x;
    const float4* W4 = reinterpret_cast<const float4*>(W);
    for (int i = tid; i < CIN * TX; i += 256) Ws[i] = W4[i];
    __syncthreads();

    int tx = tid % TX;
    int ty = tid / TX;
    int row0 = (blockIdx.x * TY + ty) * R;

    const float4* inp[R];
#pragma unroll
    for (int r = 0; r < R; r++) {
        int rc = min(row0 + r, n - 1);
        inp[r] = reinterpret_cast<const float4*>(in + (size_t)rc * CIN);
    }

    float4 acc[R];
#pragma unroll
    for (int r = 0; r < R; r++) acc[r] = make_float4(0.f, 0.f, 0.f, 0.f);

#pragma unroll 2
    for (int k4 = 0; k4 < CIN / 4; k4++) {
        float4 xv[R];
#pragma unroll
        for (int r = 0; r < R; r++) {
            xv[r] = __ldg(&inp[r][k4]);
            if (RELU) {
                xv[r].x = fmaxf(xv[r].x, 0.f); xv[r].y = fmaxf(xv[r].y, 0.f);
                xv[r].z = fmaxf(xv[r].z, 0.f); xv[r].w = fmaxf(xv[r].w, 0.f);
            }
        }
#pragma unroll
        for (int j = 0; j < 4; j++) {
            float4 w = Ws[(k4 * 4 + j) * TX + tx];
#pragma unroll
            for (int r = 0; r < R; r++) {
                float xs = (j == 0) ? xv[r].x : (j == 1) ? xv[r].y
                         : (j == 2) ? xv[r].z : xv[r].w;
                acc[r].x = fmaf(xs, w.x, acc[r].x);
                acc[r].y = fmaf(xs, w.y, acc[r].y);
                acc[r].z = fmaf(xs, w.z, acc[r].z);
                acc[r].w = fmaf(xs, w.w, acc[r].w);
            }
        }
    }

    // store h
    float4* out4 = reinterpret_cast<float4*>(g_h);
#pragma unroll
    for (int r = 0; r < R; r++) {
        int row = row0 + r;
        if (row < n) out4[(size_t)row * TX + tx] = acc[r];
    }

    // fused edot: es[row] = h[row].a_src, ed[row] = h[row].a_dst
    const float4* as4 = reinterpret_cast<const float4*>(as_);
    const float4* ad4 = reinterpret_cast<const float4*>(ad_);
    float4 av = __ldg(&as4[tx]);
    float4 dv = __ldg(&ad4[tx]);
#pragma unroll
    for (int r = 0; r < R; r++) {
        float ps = acc[r].x * av.x + acc[r].y * av.y
                 + acc[r].z * av.z + acc[r].w * av.w;
        float pd = acc[r].x * dv.x + acc[r].y * dv.y
                 + acc[r].z * dv.z + acc[r].w * dv.w;
#pragma unroll
        for (int off = TX / 2; off > 0; off >>= 1) {
            ps += __shfl_down_sync(0xffffffffu, ps, off, TX);
            pd += __shfl_down_sync(0xffffffffu, pd, off, TX);
        }
        int row = row0 + r;
        if (tx == 0 && row < n) { g_es[row] = ps; g_ed[row] = pd; }
    }
}

// -------------------- vector helpers --------------------------------------
template <int V> struct VecT;
template <> struct VecT<1> { using T = float; };
template <> struct VecT<2> { using T = float2; };
template <> struct VecT<4> { using T = float4; };

__device__ __forceinline__ void vfma(float& a, float al, float v) {
    a = fmaf(al, v, a);
}
__device__ __forceinline__ void vfma(float2& a, float al, float2 v) {
    a.x = fmaf(al, v.x, a.x); a.y = fmaf(al, v.y, a.y);
}
__device__ __forceinline__ void vfma(float4& a, float al, float4 v) {
    a.x = fmaf(al, v.x, a.x); a.y = fmaf(al, v.y, a.y);
    a.z = fmaf(al, v.z, a.z); a.w = fmaf(al, v.w, a.w);
}

// -------------------- fused edge phase: softmax + aggregate (warp/dst) ----
template <int COUT>
__global__ void gat_edge_kernel(const float* __restrict__ b,
                                float* __restrict__ agg, int n) {
    constexpr int V = COUT / 32;
    using VT = typename VecT<V>::T;
    const unsigned full = 0xffffffffu;
    int lane = threadIdx.x & 31;
    int d = blockIdx.x * 8 + (threadIdx.x >> 5);
    if (d >= n) return;

    int r0 = g_rowptr[d];
    int r1 = g_rowptr[d + 1];
    int deg = r1 - r0;
    float edd = g_ed[d];

    const VT* bv = reinterpret_cast<const VT*>(b);
    VT acc = __ldg(&bv[lane]);
    const VT* hv = reinterpret_cast<const VT*>(g_h);   // 32 vecs per row

    if (deg <= 32) {
        // ---- register-resident single-pass softmax ----
        int sidx = 0;
        float e = -3.4e38f;
        if (lane < deg) {
            sidx = __ldg(&g_csr_src[r0 + lane]);
            e = __ldg(&g_es[sidx]) + edd;
            e = (e > 0.f) ? e : 0.2f * e;
        }
        float mx = e;
#pragma unroll
        for (int o = 16; o; o >>= 1)
            mx = fmaxf(mx, __shfl_xor_sync(full, mx, o));
        float ex = (lane < deg) ? __expf(e - mx) : 0.f;
        float sum = ex;
#pragma unroll
        for (int o = 16; o; o >>= 1)
            sum += __shfl_xor_sync(full, sum, o);
        float alpha = ex / sum;

        for (int j = 0; j < deg; j++) {
            int s = __shfl_sync(full, sidx, j);
            float a = __shfl_sync(full, alpha, j);
            VT v = __ldg(&hv[(size_t)s * 32 + lane]);
            vfma(acc, a, v);
        }
    } else {
        // ---- fallback 3-phase (rare: deg > 32) ----
        float mx = -3.4e38f;
        for (int i = r0 + lane; i < r1; i += 32) {
            float e = __ldg(&g_es[__ldg(&g_csr_src[i])]) + edd;
            e = (e > 0.f) ? e : 0.2f * e;
            g_e[i] = e;
            mx = fmaxf(mx, e);
        }
#pragma unroll
        for (int o = 16; o; o >>= 1)
            mx = fmaxf(mx, __shfl_xor_sync(full, mx, o));
        float sum = 0.f;
        for (int i = r0 + lane; i < r1; i += 32) {
            float ex = __expf(g_e[i] - mx);
            g_e[i] = ex;
            sum += ex;
        }
#pragma unroll
        for (int o = 16; o; o >>= 1)
            sum += __shfl_xor_sync(full, sum, o);
        float invS = 1.0f / sum;
        __syncwarp();

#pragma unroll 4
        for (int i = r0; i < r1; i++) {
            int s = __ldg(&g_csr_src[i]);
            float a = __ldg(&g_e[i]) * invS;
            VT v = __ldg(&hv[(size_t)s * 32 + lane]);
            vfma(acc, a, v);
        }
    }

    reinterpret_cast<VT*>(agg)[(size_t)d * 32 + lane] = acc;
}

// -------------------- final FC: out = relu(agg4) @ fcW + fcb --------------
__global__ void fc_kernel(const float* __restrict__ in,
                          const float* __restrict__ fcW,
                          const float* __restrict__ fcb,
                          float* __restrict__ out, int n) {
    __shared__ float Ws[128 * 40];
    int tid = threadIdx.x;                 // blockDim = 320
    for (int i = tid; i < 128 * 40; i += 320) Ws[i] = fcW[i];
    __syncthreads();
    int tx = tid % 40;
    int ty = tid / 40;                     // 8 rows/block
    int row = blockIdx.x * 8 + ty;
    if (row >= n) return;
    const float* irow = in + (size_t)row * 128;
    float acc = 0.f;
#pragma unroll 8
    for (int k = 0; k < 128; k++) {
        float v = fmaxf(irow[k], 0.f);
        acc = fmaf(v, Ws[k * 40 + tx], acc);
    }
    out[(size_t)row * 40 + tx] = acc + fcb[tx];
}

// ---------------------------------------------------------------------------
// host driver
// ---------------------------------------------------------------------------
static inline int ceil_div(int a, int b) { return (a + b - 1) / b; }

template <int CIN, int COUT, bool RELU>
static void launch_gemm(const float* in, const float* W,
                        const float* as_, const float* ad_, int n) {
    constexpr int TX = COUT / 4;
    constexpr int TY = 256 / TX;
    constexpr int R  = 4;
    size_t smem = (size_t)CIN * TX * sizeof(float4);
    if (smem > 48 * 1024) {
        cudaFuncSetAttribute((const void*)gemm_kernel<CIN, COUT, RELU>,
                             cudaFuncAttributeMaxDynamicSharedMemorySize,
                             (int)smem);
    }
    gemm_kernel<CIN, COUT, RELU><<<ceil_div(n, TY * R), 256, smem>>>(
        in, W, as_, ad_, n);
}

extern "C" void kernel_launch(void* const* d_in, const int* in_sizes, int n_in,
                              void* d_out, int out_size) {
    const float* x   = (const float*)d_in[0];
    const void*  ei  = d_in[1];
    const float* W1  = (const float*)d_in[2];
    const float* a1s = (const float*)d_in[3];
    const float* a1d = (const float*)d_in[4];
    const float* b1  = (const float*)d_in[5];
    const float* W2  = (const float*)d_in[6];
    const float* a2s = (const float*)d_in[7];
    const float* a2d = (const float*)d_in[8];
    const float* b2  = (const float*)d_in[9];
    const float* W3  = (const float*)d_in[10];
    const float* a3s = (const float*)d_in[11];
    const float* a3d = (const float*)d_in[12];
    const float* b3  = (const float*)d_in[13];
    const float* W4  = (const float*)d_in[14];
    const float* a4s = (const float*)d_in[15];
    const float* a4d = (const float*)d_in[16];
    const float* b4  = (const float*)d_in[17];
    const float* fcW = (const float*)d_in[18];
    const float* fcb = (const float*)d_in[19];

    const int n = in_sizes[0] / 256;
    const int E = in_sizes[1] / 2;
    const int tot = E + n;

    float* aggA; cudaGetSymbolAddress((void**)&aggA, g_aggA);
    float* aggB; cudaGetSymbolAddress((void**)&aggB, g_aggB);

    // ---- preprocessing; gemm1 placed 4th in stream order for profiling ----
    detect_init_kernel<<<ceil_div(n, 256), 256>>>(ei, n);       // 1
    convert_count_kernel<<<ceil_div(E, 256), 256>>>(ei, E);     // 2
    scan_kernel<<<1, 1024>>>(n);                                // 3
    launch_gemm<256, 32, false>(x, W1, a1s, a1d, n);            // 4 (profiled)
    scatter_kernel<<<ceil_div(tot, 256), 256>>>(E, n);          // 5

    // ---- layer 1: 256 -> 32 ----
    gat_edge_kernel<32><<<ceil_div(n, 8), 256>>>(b1, aggA, n);

    // ---- layer 2: 32 -> 64 ----
    launch_gemm<32, 64, true>(aggA, W2, a2s, a2d, n);
    gat_edge_kernel<64><<<ceil_div(n, 8), 256>>>(b2, aggB, n);

    // ---- layer 3: 64 -> 128 ----
    launch_gemm<64, 128, true>(aggB, W3, a3s, a3d, n);
    gat_edge_kernel<128><<<ceil_div(n, 8), 256>>>(b3, aggA, n);

    // ---- layer 4: 128 -> 128 ----
    launch_gemm<128, 128, true>(aggA, W4, a4s, a4d, n);
    gat_edge_kernel<128><<<ceil_div(n, 8), 256>>>(b4, aggB, n);

    // ---- final fc: relu(agg4) @ fcW + fcb ----
    fc_kernel<<<ceil_div(n, 8), 320>>>(aggB, fcW, fcb, (float*)d_out, n);
}

// round 6
// speedup vs baseline: 1.1519x; 1.0088x over previous
#include <cuda_runtime.h>
#include <cstdint>

// ---------------------------------------------------------------------------
// GAT 4-layer network, N=50000 nodes, E=800000 edges (+ N self-loops).
// dims: 256 -> 32 -> 64 -> 128 -> 128 -> fc 40
// R6: single-pass edge kernel with smem-staged (src,alpha) broadcast and
//     4x-unrolled gathers; fused-edot SIMT GEMM; slim preprocess.
// ---------------------------------------------------------------------------

#define NMAX 50000
#define EMAX 800000
#define CMAX 128
#define TOTE (EMAX + NMAX)

// -------------------- device scratch (allocation-free rule) ---------------
__device__ int      g_src[EMAX];
__device__ int      g_dst[EMAX];
__device__ int      g_cnt[NMAX];
__device__ int      g_rowptr[NMAX + 1];
__device__ int      g_cursor[NMAX];
__device__ int      g_csr_src[TOTE];
__device__ float    g_e[TOTE];
__device__ __align__(16) float g_h[(size_t)NMAX * CMAX];
__device__ __align__(16) float g_aggA[(size_t)NMAX * CMAX];
__device__ __align__(16) float g_aggB[(size_t)NMAX * CMAX];
__device__ float    g_es[NMAX];
__device__ float    g_ed[NMAX];
__device__ int      g_is64;

// -------------------- detect edge dtype + init counts ---------------------
__global__ void detect_init_kernel(const void* eptr, int n) {
    int i = blockIdx.x * blockDim.x + threadIdx.x;
    if (i < n) g_cnt[i] = 1;              // self-loop pre-counted
    if (i == 0) {
        const int* p = (const int*)eptr;
        int all0 = 1;
        for (int k = 1; k < 128; k += 2)
            if (p[k] != 0) all0 = 0;
        g_is64 = all0;   // int64 little-endian, values < 2^31 -> odd words 0
    }
}

// -------------------- convert + count (fused) ------------------------------
__global__ void convert_count_kernel(const void* eptr, int E) {
    int i = blockIdx.x * blockDim.x + threadIdx.x;
    if (i >= E) return;
    int s, d;
    if (g_is64) {
        const long long* p = (const long long*)eptr;
        s = (int)p[i];
        d = (int)p[E + i];
    } else {
        const int* p = (const int*)eptr;
        s = p[i];
        d = p[E + i];
    }
    g_src[i] = s;
    g_dst[i] = d;
    atomicAdd(&g_cnt[d], 1);
}

// -------------------- single-block exclusive scan over g_cnt --------------
__global__ void scan_kernel(int n) {
    const int T = 1024;
    int tid = threadIdx.x;
    int C = (n + T - 1) / T;
    int base = tid * C;
    int end = min(base + C, n);

    int s = 0;
    for (int k = base; k < end; k++) s += g_cnt[k];

    int lane = tid & 31, w = tid >> 5;
    unsigned full = 0xffffffffu;
    int x = s;
#pragma unroll
    for (int o = 1; o < 32; o <<= 1) {
        int y = __shfl_up_sync(full, x, o);
        if (lane >= o) x += y;
    }
    __shared__ int wsum[32];
    __shared__ int woff[32];
    if (lane == 31) wsum[w] = x;
    __syncthreads();
    if (tid < 32) {
        int v = wsum[tid];
        int xx = v;
#pragma unroll
        for (int o = 1; o < 32; o <<= 1) {
            int y = __shfl_up_sync(full, xx, o);
            if (tid >= o) xx += y;
        }
        woff[tid] = xx - v;
    }
    __syncthreads();
    int running = x - s + woff[w];

    for (int k = base; k < end; k++) {
        g_rowptr[k] = running;
        g_cursor[k] = running;
        running += g_cnt[k];
    }
    if (end == n && base < n) g_rowptr[n] = running;
}

__global__ void scatter_kernel(int E, int n) {
    int idx = blockIdx.x * blockDim.x + threadIdx.x;
    if (idx >= E + n) return;
    int s, d;
    if (idx < E) { s = g_src[idx]; d = g_dst[idx]; }
    else         { s = d = idx - E; }
    int pos = atomicAdd(&g_cursor[d], 1);
    g_csr_src[pos] = s;
}

// -------------------- GEMM + fused edot: h = act(in)@W; es,ed dots --------
template <int CIN, int COUT, bool RELU>
__global__ void gemm_kernel(const float* __restrict__ in,
                            const float* __restrict__ W,
                            const float* __restrict__ as_,
                            const float* __restrict__ ad_, int n) {
    constexpr int TX = COUT / 4;       // threads along column dim (float4 each)
    constexpr int TY = 256 / TX;       // thread-rows per block
    constexpr int R  = 4;              // rows per thread
    extern __shared__ float4 Ws[];     // CIN * TX float4

    int tid = threadIdx.x;
    const float4* W4 = reinterpret_cast<const float4*>(W);
    for (int i = tid; i < CIN * TX; i += 256) Ws[i] = W4[i];
    __syncthreads();

    int tx = tid % TX;
    int ty = tid / TX;
    int row0 = (blockIdx.x * TY + ty) * R;

    const float4* inp[R];
#pragma unroll
    for (int r = 0; r < R; r++) {
        int rc = min(row0 + r, n - 1);
        inp[r] = reinterpret_cast<const float4*>(in + (size_t)rc * CIN);
    }

    float4 acc[R];
#pragma unroll
    for (int r = 0; r < R; r++) acc[r] = make_float4(0.f, 0.f, 0.f, 0.f);

#pragma unroll 2
    for (int k4 = 0; k4 < CIN / 4; k4++) {
        float4 xv[R];
#pragma unroll
        for (int r = 0; r < R; r++) {
            xv[r] = __ldg(&inp[r][k4]);
            if (RELU) {
                xv[r].x = fmaxf(xv[r].x, 0.f); xv[r].y = fmaxf(xv[r].y, 0.f);
                xv[r].z = fmaxf(xv[r].z, 0.f); xv[r].w = fmaxf(xv[r].w, 0.f);
            }
        }
#pragma unroll
        for (int j = 0; j < 4; j++) {
            float4 w = Ws[(k4 * 4 + j) * TX + tx];
#pragma unroll
            for (int r = 0; r < R; r++) {
                float xs = (j == 0) ? xv[r].x : (j == 1) ? xv[r].y
                         : (j == 2) ? xv[r].z : xv[r].w;
                acc[r].x = fmaf(xs, w.x, acc[r].x);
                acc[r].y = fmaf(xs, w.y, acc[r].y);
                acc[r].z = fmaf(xs, w.z, acc[r].z);
                acc[r].w = fmaf(xs, w.w, acc[r].w);
            }
        }
    }

    // store h
    float4* out4 = reinterpret_cast<float4*>(g_h);
#pragma unroll
    for (int r = 0; r < R; r++) {
        int row = row0 + r;
        if (row < n) out4[(size_t)row * TX + tx] = acc[r];
    }

    // fused edot: es[row] = h[row].a_src, ed[row] = h[row].a_dst
    const float4* as4 = reinterpret_cast<const float4*>(as_);
    const float4* ad4 = reinterpret_cast<const float4*>(ad_);
    float4 av = __ldg(&as4[tx]);
    float4 dv = __ldg(&ad4[tx]);
#pragma unroll
    for (int r = 0; r < R; r++) {
        float ps = acc[r].x * av.x + acc[r].y * av.y
                 + acc[r].z * av.z + acc[r].w * av.w;
        float pd = acc[r].x * dv.x + acc[r].y * dv.y
                 + acc[r].z * dv.z + acc[r].w * dv.w;
#pragma unroll
        for (int off = TX / 2; off > 0; off >>= 1) {
            ps += __shfl_down_sync(0xffffffffu, ps, off, TX);
            pd += __shfl_down_sync(0xffffffffu, pd, off, TX);
        }
        int row = row0 + r;
        if (tx == 0 && row < n) { g_es[row] = ps; g_ed[row] = pd; }
    }
}

// -------------------- vector helpers --------------------------------------
template <int V> struct VecT;
template <> struct VecT<1> { using T = float; };
template <> struct VecT<2> { using T = float2; };
template <> struct VecT<4> { using T = float4; };

__device__ __forceinline__ void vfma(float& a, float al, float v) {
    a = fmaf(al, v, a);
}
__device__ __forceinline__ void vfma(float2& a, float al, float2 v) {
    a.x = fmaf(al, v.x, a.x); a.y = fmaf(al, v.y, a.y);
}
__device__ __forceinline__ void vfma(float4& a, float al, float4 v) {
    a.x = fmaf(al, v.x, a.x); a.y = fmaf(al, v.y, a.y);
    a.z = fmaf(al, v.z, a.z); a.w = fmaf(al, v.w, a.w);
}

// -------------------- fused edge phase: softmax + aggregate (warp/dst) ----
// deg<=32 fast path: per-lane alpha staged into smem, gathers unrolled x4.
template <int COUT>
__global__ void gat_edge_kernel(const float* __restrict__ b,
                                float* __restrict__ agg, int n) {
    constexpr int V = COUT / 32;
    using VT = typename VecT<V>::T;
    const unsigned full = 0xffffffffu;
    __shared__ float salpha[8][32];
    __shared__ int   ssrc[8][32];

    int lane = threadIdx.x & 31;
    int w = threadIdx.x >> 5;
    int d = blockIdx.x * 8 + w;
    if (d >= n) return;

    int r0 = g_rowptr[d];
    int r1 = g_rowptr[d + 1];
    int deg = r1 - r0;
    float edd = g_ed[d];

    const VT* bv = reinterpret_cast<const VT*>(b);
    VT acc = __ldg(&bv[lane]);
    const VT* hv = reinterpret_cast<const VT*>(g_h);   // 32 vecs per row

    if (deg <= 32) {
        // ---- single-pass softmax, alpha in registers -> smem ----
        int sidx = 0;
        float e = -3.4e38f;
        if (lane < deg) {
            sidx = __ldg(&g_csr_src[r0 + lane]);
            e = __ldg(&g_es[sidx]) + edd;
            e = (e > 0.f) ? e : 0.2f * e;
        }
        float mx = e;
#pragma unroll
        for (int o = 16; o; o >>= 1)
            mx = fmaxf(mx, __shfl_xor_sync(full, mx, o));
        float ex = (lane < deg) ? __expf(e - mx) : 0.f;
        float sum = ex;
#pragma unroll
        for (int o = 16; o; o >>= 1)
            sum += __shfl_xor_sync(full, sum, o);

        ssrc[w][lane] = sidx;
        salpha[w][lane] = ex / sum;
        __syncwarp();

        // ---- gather, unrolled x4 for MLP ----
        int j = 0;
        for (; j + 4 <= deg; j += 4) {
            int s0 = ssrc[w][j],     s1 = ssrc[w][j + 1];
            int s2 = ssrc[w][j + 2], s3 = ssrc[w][j + 3];
            float a0 = salpha[w][j],     a1 = salpha[w][j + 1];
            float a2 = salpha[w][j + 2], a3 = salpha[w][j + 3];
            VT v0 = __ldg(&hv[(size_t)s0 * 32 + lane]);
            VT v1 = __ldg(&hv[(size_t)s1 * 32 + lane]);
            VT v2 = __ldg(&hv[(size_t)s2 * 32 + lane]);
            VT v3 = __ldg(&hv[(size_t)s3 * 32 + lane]);
            vfma(acc, a0, v0);
            vfma(acc, a1, v1);
            vfma(acc, a2, v2);
            vfma(acc, a3, v3);
        }
        for (; j < deg; j++) {
            int s = ssrc[w][j];
            float a = salpha[w][j];
            VT v = __ldg(&hv[(size_t)s * 32 + lane]);
            vfma(acc, a, v);
        }
    } else {
        // ---- fallback 3-phase (rare: deg > 32) ----
        float mx = -3.4e38f;
        for (int i = r0 + lane; i < r1; i += 32) {
            float e = __ldg(&g_es[__ldg(&g_csr_src[i])]) + edd;
            e = (e > 0.f) ? e : 0.2f * e;
            g_e[i] = e;
            mx = fmaxf(mx, e);
        }
#pragma unroll
        for (int o = 16; o; o >>= 1)
            mx = fmaxf(mx, __shfl_xor_sync(full, mx, o));
        float sum = 0.f;
        for (int i = r0 + lane; i < r1; i += 32) {
            float ex = __expf(g_e[i] - mx);
            g_e[i] = ex;
            sum += ex;
        }
#pragma unroll
        for (int o = 16; o; o >>= 1)
            sum += __shfl_xor_sync(full, sum, o);
        float invS = 1.0f / sum;
        __syncwarp();

#pragma unroll 4
        for (int i = r0; i < r1; i++) {
            int s = __ldg(&g_csr_src[i]);
            float a = __ldg(&g_e[i]) * invS;
            VT v = __ldg(&hv[(size_t)s * 32 + lane]);
            vfma(acc, a, v);
        }
    }

    reinterpret_cast<VT*>(agg)[(size_t)d * 32 + lane] = acc;
}

// -------------------- final FC: out = relu(agg4) @ fcW + fcb --------------
__global__ void fc_kernel(const float* __restrict__ in,
                          const float* __restrict__ fcW,
                          const float* __restrict__ fcb,
                          float* __restrict__ out, int n) {
    __shared__ float Ws[128 * 40];
    int tid = threadIdx.x;                 // blockDim = 320
    for (int i = tid; i < 128 * 40; i += 320) Ws[i] = fcW[i];
    __syncthreads();
    int tx = tid % 40;
    int ty = tid / 40;                     // 8 rows/block
    int row = blockIdx.x * 8 + ty;
    if (row >= n) return;
    const float* irow = in + (size_t)row * 128;
    float acc = 0.f;
#pragma unroll 8
    for (int k = 0; k < 128; k++) {
        float v = fmaxf(irow[k], 0.f);
        acc = fmaf(v, Ws[k * 40 + tx], acc);
    }
    out[(size_t)row * 40 + tx] = acc + fcb[tx];
}

// ---------------------------------------------------------------------------
// host driver
// ---------------------------------------------------------------------------
static inline int ceil_div(int a, int b) { return (a + b - 1) / b; }

template <int CIN, int COUT, bool RELU>
static void launch_gemm(const float* in, const float* W,
                        const float* as_, const float* ad_, int n) {
    constexpr int TX = COUT / 4;
    constexpr int TY = 256 / TX;
    constexpr int R  = 4;
    size_t smem = (size_t)CIN * TX * sizeof(float4);
    if (smem > 48 * 1024) {
        cudaFuncSetAttribute((const void*)gemm_kernel<CIN, COUT, RELU>,
                             cudaFuncAttributeMaxDynamicSharedMemorySize,
                             (int)smem);
    }
    gemm_kernel<CIN, COUT, RELU><<<ceil_div(n, TY * R), 256, smem>>>(
        in, W, as_, ad_, n);
}

extern "C" void kernel_launch(void* const* d_in, const int* in_sizes, int n_in,
                              void* d_out, int out_size) {
    const float* x   = (const float*)d_in[0];
    const void*  ei  = d_in[1];
    const float* W1  = (const float*)d_in[2];
    const float* a1s = (const float*)d_in[3];
    const float* a1d = (const float*)d_in[4];
    const float* b1  = (const float*)d_in[5];
    const float* W2  = (const float*)d_in[6];
    const float* a2s = (const float*)d_in[7];
    const float* a2d = (const float*)d_in[8];
    const float* b2  = (const float*)d_in[9];
    const float* W3  = (const float*)d_in[10];
    const float* a3s = (const float*)d_in[11];
    const float* a3d = (const float*)d_in[12];
    const float* b3  = (const float*)d_in[13];
    const float* W4  = (const float*)d_in[14];
    const float* a4s = (const float*)d_in[15];
    const float* a4d = (const float*)d_in[16];
    const float* b4  = (const float*)d_in[17];
    const float* fcW = (const float*)d_in[18];
    const float* fcb = (const float*)d_in[19];

    const int n = in_sizes[0] / 256;
    const int E = in_sizes[1] / 2;
    const int tot = E + n;

    float* aggA; cudaGetSymbolAddress((void**)&aggA, g_aggA);
    float* aggB; cudaGetSymbolAddress((void**)&aggB, g_aggB);

    // ---- preprocessing; gemm1 placed 4th in stream order for profiling ----
    detect_init_kernel<<<ceil_div(n, 256), 256>>>(ei, n);       // 1
    convert_count_kernel<<<ceil_div(E, 256), 256>>>(ei, E);     // 2
    scan_kernel<<<1, 1024>>>(n);                                // 3
    launch_gemm<256, 32, false>(x, W1, a1s, a1d, n);            // 4 (profiled)
    scatter_kernel<<<ceil_div(tot, 256), 256>>>(E, n);          // 5

    // ---- layer 1: 256 -> 32 ----
    gat_edge_kernel<32><<<ceil_div(n, 8), 256>>>(b1, aggA, n);

    // ---- layer 2: 32 -> 64 ----
    launch_gemm<32, 64, true>(aggA, W2, a2s, a2d, n);
    gat_edge_kernel<64><<<ceil_div(n, 8), 256>>>(b2, aggB, n);

    // ---- layer 3: 64 -> 128 ----
    launch_gemm<64, 128, true>(aggB, W3, a3s, a3d, n);
    gat_edge_kernel<128><<<ceil_div(n, 8), 256>>>(b3, aggA, n);

    // ---- layer 4: 128 -> 128 ----
    launch_gemm<128, 128, true>(aggA, W4, a4s, a4d, n);
    gat_edge_kernel<128><<<ceil_div(n, 8), 256>>>(b4, aggB, n);

    // ---- final fc: relu(agg4) @ fcW + fcb ----
    fc_kernel<<<ceil_div(n, 8), 320>>>(aggB, fcW, fcb, (float*)d_out, n);
}